// round 3
// baseline (speedup 1.0000x reference)
#include <cuda_runtime.h>

// ---------------------------------------------------------------------------
// Bit-exact-targeting fused SNN kernel. One CTA per batch element, T=100
// steps in-kernel. Replicates XLA:CPU (Eigen) arithmetic:
//   - conv: per-output single accumulator, sequential FMA in (ky, kx, ic)
//     order (ic innermost == Eigen RowMajor im2col GEMM K order)
//   - FC: sequential FMA over k = 0..799 (flatten order oc*25+i*5+j)
//   - LIF: CONTRACTED form (LLVM fast-math FMA): m' = fma(beta,m,cur) - reset
//   - bias added after pool (bitwise == before pool: max is exact+monotone)
// ---------------------------------------------------------------------------

#define T_STEPS 100
#define BATCH   256

// smem layout (float offsets)
constexpr int OFF_W1 = 0;        // w1cl [12][5][5][2]  = 600
constexpr int OFF_B1 = 600;      // 12
constexpr int OFF_W2 = 612;      // w2cl [32][5][5][12] = 9600
constexpr int OFF_B2 = 10212;    // 32
constexpr int OFF_W3 = 10244;    // [10][800] = 8000
constexpr int OFF_B3 = 18244;    // 10 (+2 pad)
constexpr int OFF_X  = 18256;    // x channels-last [32][32][2] = 2048
constexpr int OFF_S1 = 20304;    // spk1 cl [14 rows][16 cols pad][12 ic] = 2688
constexpr int OFF_M1 = 22992;    // 2688
constexpr int OFF_S2 = 25680;    // 800 (oc*25 + i*5 + j)
constexpr int OFF_M2 = 26480;    // 800
constexpr int OFF_M3 = 27280;    // 16
constexpr int SMEM_FLOATS = 27296;
constexpr int SMEM_BYTES  = SMEM_FLOATS * 4;

// LIF, snntorch 'subtract', XLA:CPU fast-math contracted:
//   m' = fsub(fma(0.95, m, cur), reset)
__device__ __forceinline__ float lif_exact(float* mem, float cur) {
    float m = *mem;
    float reset = (m > 1.0f) ? 1.0f : 0.0f;
    float mn = __fsub_rn(__fmaf_rn(0.95f, m, cur), reset);
    *mem = mn;
    return (mn > 1.0f) ? 1.0f : 0.0f;
}

__global__ void __launch_bounds__(256, 2) snn_kernel(
    const float* __restrict__ x,
    const float* __restrict__ W1, const float* __restrict__ b1,
    const float* __restrict__ W2, const float* __restrict__ b2,
    const float* __restrict__ W3, const float* __restrict__ b3,
    float* __restrict__ out)
{
    extern __shared__ float s[];
    const int b   = blockIdx.x;
    const int tid = threadIdx.x;

    // --- weights -> smem (reordered channels-last), zero state ---
    for (int i = tid; i < 600; i += 256) {
        int oc = i / 50, r = i % 50, ic = r / 25, k = r % 25;
        s[OFF_W1 + (oc * 25 + k) * 2 + ic] = W1[i];
    }
    for (int i = tid; i < 9600; i += 256) {
        int oc = i / 300, r = i % 300, ic = r / 25, k = r % 25;
        s[OFF_W2 + (oc * 25 + k) * 12 + ic] = W2[i];
    }
    for (int i = tid; i < 8000; i += 256) s[OFF_W3 + i] = W3[i];
    for (int i = tid; i < 12;   i += 256) s[OFF_B1 + i] = b1[i];
    for (int i = tid; i < 32;   i += 256) s[OFF_B2 + i] = b2[i];
    for (int i = tid; i < 12;   i += 256) s[OFF_B3 + i] = (i < 10) ? b3[i] : 0.f;
    for (int i = tid; i < 2688; i += 256) { s[OFF_S1 + i] = 0.f; s[OFF_M1 + i] = 0.f; }
    for (int i = tid; i < 800;  i += 256) { s[OFF_S2 + i] = 0.f; s[OFF_M2 + i] = 0.f; }
    if (tid < 16) s[OFF_M3 + tid] = 0.f;
    __syncthreads();

    for (int t = 0; t < T_STEPS; t++) {
        // --- x[t][b] -> smem channels-last [32][32][2] ---
        const float* xg = x + ((long long)t * BATCH + b) * 2048;
        for (int idx = tid; idx < 2048; idx += 256) {
            int pos = idx >> 1, ic = idx & 1;
            s[OFF_X + idx] = xg[ic * 1024 + pos];
        }
        __syncthreads();

        // --- stage 1: conv1(2->12) + pool + LIF ---
        // 196 tasks: (14 rows x 7 col-pairs) x 2 oc-halves; 48 accumulators
        if (tid < 196) {
            int ocg = tid & 1, pos = tid >> 1;
            int i = pos / 7, jp = pos % 7;
            int cbase = 4 * jp;
            int ocb = ocg * 6;
            float acc[48];
            #pragma unroll
            for (int k = 0; k < 48; k++) acc[k] = 0.f;

            for (int ry = 0; ry < 6; ry++) {
                const float2* xr = reinterpret_cast<const float2*>(
                    s + OFF_X + ((2 * i + ry) * 32 + cbase) * 2);
                float2 win[8];
                #pragma unroll
                for (int c = 0; c < 8; c++) win[c] = xr[c];
                bool top = (ry < 5), bot = (ry > 0);
                int kyt = top ? ry : 4;          // clamped (selected to 0 below)
                int kyb = bot ? ry - 1 : 0;
                #pragma unroll
                for (int kx = 0; kx < 5; kx++) {
                    #pragma unroll
                    for (int oc = 0; oc < 6; oc++) {
                        float2 wt = *reinterpret_cast<const float2*>(
                            s + OFF_W1 + (((ocb + oc) * 5 + kyt) * 5 + kx) * 2);
                        float2 wb = *reinterpret_cast<const float2*>(
                            s + OFF_W1 + (((ocb + oc) * 5 + kyb) * 5 + kx) * 2);
                        if (!top) { wt.x = 0.f; wt.y = 0.f; }  // fmaf(0,x,a)==a exact
                        if (!bot) { wb.x = 0.f; wb.y = 0.f; }
                        #pragma unroll
                        for (int c = 0; c < 4; c++) {
                            float2 xv = win[kx + c];
                            float a0 = acc[oc * 8 + c];
                            float a1 = acc[oc * 8 + 4 + c];
                            a0 = fmaf(wt.x, xv.x, a0);
                            a0 = fmaf(wt.y, xv.y, a0);
                            a1 = fmaf(wb.x, xv.x, a1);
                            a1 = fmaf(wb.y, xv.y, a1);
                            acc[oc * 8 + c]     = a0;
                            acc[oc * 8 + 4 + c] = a1;
                        }
                    }
                }
            }
            #pragma unroll
            for (int oc = 0; oc < 6; oc++) {
                float p0 = fmaxf(fmaxf(acc[oc*8+0], acc[oc*8+1]),
                                 fmaxf(acc[oc*8+4], acc[oc*8+5]));
                float p1 = fmaxf(fmaxf(acc[oc*8+2], acc[oc*8+3]),
                                 fmaxf(acc[oc*8+6], acc[oc*8+7]));
                float bias = s[OFF_B1 + ocb + oc];
                int idx0 = (i * 16 + 2 * jp) * 12 + (ocb + oc);
                s[OFF_S1 + idx0] = lif_exact(&s[OFF_M1 + idx0], __fadd_rn(p0, bias));
                int idx1 = idx0 + 12;
                s[OFF_S1 + idx1] = lif_exact(&s[OFF_M1 + idx1], __fadd_rn(p1, bias));
            }
        }
        __syncthreads();

        // --- stage 2: conv2(12->32) + pool + LIF ---
        // 480 tasks: 32 oc x 5 rows x 3 col-pair groups (last ragged)
        for (int task = tid; task < 480; task += 256) {
            int oc = task / 15, rem = task % 15;
            int i = rem / 3, jpp = rem % 3;
            int cbase = 4 * jpp;
            float acc[8];
            #pragma unroll
            for (int k = 0; k < 8; k++) acc[k] = 0.f;

            for (int ry = 0; ry < 6; ry++) {
                const float4* xr = reinterpret_cast<const float4*>(
                    s + OFF_S1 + ((2 * i + ry) * 16 + cbase) * 12);
                float4 xw[12];                  // rolling 4-col window, 3 f4/col
                #pragma unroll
                for (int c = 0; c < 4; c++)
                    #pragma unroll
                    for (int k = 0; k < 3; k++) xw[c * 3 + k] = xr[c * 3 + k];
                bool top = (ry < 5), bot = (ry > 0);
                int kyt = top ? ry : 4;
                int kyb = bot ? ry - 1 : 0;
                const float* wtp = s + OFF_W2 + (oc * 5 + kyt) * 5 * 12;
                const float* wbp = s + OFF_W2 + (oc * 5 + kyb) * 5 * 12;
                #pragma unroll
                for (int kx = 0; kx < 5; kx++) {
                    float4 wtv[3], wbv[3];
                    #pragma unroll
                    for (int k = 0; k < 3; k++) {
                        float4 t0 = reinterpret_cast<const float4*>(wtp + kx * 12)[k];
                        float4 b0 = reinterpret_cast<const float4*>(wbp + kx * 12)[k];
                        if (!top) { t0.x=0.f; t0.y=0.f; t0.z=0.f; t0.w=0.f; }
                        if (!bot) { b0.x=0.f; b0.y=0.f; b0.z=0.f; b0.w=0.f; }
                        wtv[k] = t0; wbv[k] = b0;
                    }
                    #pragma unroll
                    for (int c = 0; c < 4; c++) {
                        float a0 = acc[c], a1 = acc[4 + c];
                        #pragma unroll
                        for (int k = 0; k < 3; k++) {
                            float4 xv = xw[((kx + c) & 3) * 3 + k];
                            a0 = fmaf(wtv[k].x, xv.x, a0);
                            a0 = fmaf(wtv[k].y, xv.y, a0);
                            a0 = fmaf(wtv[k].z, xv.z, a0);
                            a0 = fmaf(wtv[k].w, xv.w, a0);
                            a1 = fmaf(wbv[k].x, xv.x, a1);
                            a1 = fmaf(wbv[k].y, xv.y, a1);
                            a1 = fmaf(wbv[k].z, xv.z, a1);
                            a1 = fmaf(wbv[k].w, xv.w, a1);
                        }
                        acc[c] = a0; acc[4 + c] = a1;
                    }
                    if (kx < 4) {               // slide window: bring in col kx+4
                        #pragma unroll
                        for (int k = 0; k < 3; k++)
                            xw[(kx & 3) * 3 + k] = xr[(kx + 4) * 3 + k];
                    }
                }
            }
            float bias = s[OFF_B2 + oc];
            float p0 = fmaxf(fmaxf(acc[0], acc[1]), fmaxf(acc[4], acc[5]));
            float p1 = fmaxf(fmaxf(acc[2], acc[3]), fmaxf(acc[6], acc[7]));
            int j0 = 2 * jpp;
            int idx = oc * 25 + i * 5 + j0;
            s[OFF_S2 + idx] = lif_exact(&s[OFF_M2 + idx], __fadd_rn(p0, bias));
            if (j0 + 1 < 5) {
                s[OFF_S2 + idx + 1] =
                    lif_exact(&s[OFF_M2 + idx + 1], __fadd_rn(p1, bias));
            }
        }
        __syncthreads();

        // --- stage 3: FC(800->10) + LIF, strict sequential k order ---
        if (tid < 10) {
            const float* wrow = s + OFF_W3 + tid * 800;
            const float* s2   = s + OFF_S2;
            float acc = 0.f;
            #pragma unroll 8
            for (int q = 0; q < 800; q++)
                acc = fmaf(s2[q], wrow[q], acc);
            float cur = __fadd_rn(acc, s[OFF_B3 + tid]);
            float spk = lif_exact(&s[OFF_M3 + tid], cur);
            out[((long long)t * BATCH + b) * 10 + tid] = spk;
        }
        // stage 3 regions don't overlap next iteration's x-load; the barrier
        // after the x-load orders everything else.
    }
}

extern "C" void kernel_launch(void* const* d_in, const int* in_sizes, int n_in,
                              void* d_out, int out_size) {
    const float* x  = (const float*)d_in[0];
    const float* W1 = (const float*)d_in[1];
    const float* b1 = (const float*)d_in[2];
    const float* W2 = (const float*)d_in[3];
    const float* b2 = (const float*)d_in[4];
    const float* W3 = (const float*)d_in[5];
    const float* b3 = (const float*)d_in[6];
    float* out = (float*)d_out;

    cudaFuncSetAttribute(snn_kernel,
                         cudaFuncAttributeMaxDynamicSharedMemorySize,
                         SMEM_BYTES);
    snn_kernel<<<BATCH, 256, SMEM_BYTES>>>(x, W1, b1, W2, b2, W3, b3, out);
}

// round 4
// speedup vs baseline: 2.4150x; 2.4150x over previous
#include <cuda_runtime.h>

// ---------------------------------------------------------------------------
// Bit-exact fused SNN kernel, v2 (performance restructure of the passing R3).
// One CTA per batch element, T=100 steps in-kernel.
// Arithmetic chains (PROTECTED, bit-exact vs reference):
//   conv: per-output sequential FMA in (ky, kx, ic) order
//   FC:   sequential FMA q = 0..799
//   LIF:  m' = fsub(fma(0.95, m, cur), reset)
//   pool-then-bias (max exact+monotone)
// Performance changes vs R3:
//   - stage2: lane = oc, warp = pooled position -> x loads broadcast,
//     weight f4 loads conflict-free; rolling 2-col register window
//   - membrane state in registers (stable thread ownership)
//   - stage3 float4 + padded W3 rows (804), overlapped with next step's
//     x-load + stage1 via named barrier (warp 0 vs warps 1-7)
//   - x smem row stride padded to 66
// ---------------------------------------------------------------------------

#define T_STEPS 100
#define BATCH   256

// smem layout (float offsets)
constexpr int OFF_W1 = 0;        // w1cl [12][5][5][2]  = 600
constexpr int OFF_B1 = 600;      // 12 (+4 pad)
constexpr int OFF_W2 = 616;      // w2cl [32][25][12]   = 9600 (oc stride 300)
constexpr int OFF_B2 = 10216;    // 32
constexpr int OFF_W3 = 10248;    // [10][804]           = 8040
constexpr int OFF_B3 = 18288;    // 12
constexpr int OFF_X  = 18300;    // x cl [32 rows][66]  = 2112 (row pad 64->66)
constexpr int OFF_S1 = 20412;    // spk1 cl [14][14][12] = 2352
constexpr int OFF_S2 = 22764;    // 800 (oc*25 + i*5 + j)
constexpr int SMEM_FLOATS = 23564;
constexpr int SMEM_BYTES  = SMEM_FLOATS * 4;

// 12 sequential FMAs in ic order (chain-order protected)
__device__ __forceinline__ void fma12(float& acc,
                                      const float4& w0, const float4& w1,
                                      const float4& w2, const float4* x) {
    acc = fmaf(w0.x, x[0].x, acc);
    acc = fmaf(w0.y, x[0].y, acc);
    acc = fmaf(w0.z, x[0].z, acc);
    acc = fmaf(w0.w, x[0].w, acc);
    acc = fmaf(w1.x, x[1].x, acc);
    acc = fmaf(w1.y, x[1].y, acc);
    acc = fmaf(w1.z, x[1].z, acc);
    acc = fmaf(w1.w, x[1].w, acc);
    acc = fmaf(w2.x, x[2].x, acc);
    acc = fmaf(w2.y, x[2].y, acc);
    acc = fmaf(w2.z, x[2].z, acc);
    acc = fmaf(w2.w, x[2].w, acc);
}

// FC row k: strict sequential q=0..799 chain, then LIF, then store.
__device__ __forceinline__ void fc_stage(const float* __restrict__ s,
                                         float& mem3, int t, int b, int k,
                                         float* __restrict__ out) {
    const float4* wr = reinterpret_cast<const float4*>(s + OFF_W3 + k * 804);
    const float4* xv = reinterpret_cast<const float4*>(s + OFF_S2);
    float acc = 0.f;
    #pragma unroll 4
    for (int q = 0; q < 200; q++) {
        float4 w = wr[q], x = xv[q];
        acc = fmaf(x.x, w.x, acc);
        acc = fmaf(x.y, w.y, acc);
        acc = fmaf(x.z, w.z, acc);
        acc = fmaf(x.w, w.w, acc);
    }
    float cur = __fadd_rn(acc, s[OFF_B3 + k]);
    float reset = (mem3 > 1.0f) ? 1.0f : 0.0f;
    float mn = __fsub_rn(__fmaf_rn(0.95f, mem3, cur), reset);
    mem3 = mn;
    out[((long long)t * BATCH + b) * 10 + k] = (mn > 1.0f) ? 1.0f : 0.0f;
}

__global__ void __launch_bounds__(256, 2) snn_kernel(
    const float* __restrict__ x,
    const float* __restrict__ W1, const float* __restrict__ b1,
    const float* __restrict__ W2, const float* __restrict__ b2,
    const float* __restrict__ W3, const float* __restrict__ b3,
    float* __restrict__ out)
{
    extern __shared__ float s[];
    const int b    = blockIdx.x;
    const int tid  = threadIdx.x;
    const int lane = tid & 31;
    const int w    = tid >> 5;

    // --- weights -> smem (channels-last / padded), all 256 threads ---
    for (int i = tid; i < 600; i += 256) {
        int oc = i / 50, r = i % 50, ic = r / 25, k = r % 25;
        s[OFF_W1 + (oc * 25 + k) * 2 + ic] = W1[i];
    }
    for (int i = tid; i < 9600; i += 256) {
        int oc = i / 300, r = i % 300, ic = r / 25, k = r % 25;
        s[OFF_W2 + oc * 300 + k * 12 + ic] = W2[i];
    }
    for (int i = tid; i < 8000; i += 256) {
        int k = i / 800, q = i % 800;
        s[OFF_W3 + k * 804 + q] = W3[i];
    }
    for (int i = tid; i < 12; i += 256) s[OFF_B1 + i] = b1[i];
    for (int i = tid; i < 32; i += 256) s[OFF_B2 + i] = b2[i];
    for (int i = tid; i < 12; i += 256) s[OFF_B3 + i] = (i < 10) ? b3[i] : 0.f;
    __syncthreads();

    // --- membrane state in registers (stable thread ownership) ---
    float mem1r[12];                    // stage1: threads 32..227, 6oc x 2cols
    #pragma unroll
    for (int k = 0; k < 12; k++) mem1r[k] = 0.f;
    float mem2r[4];                     // stage2: lane=oc, up to 4 positions
    #pragma unroll
    for (int k = 0; k < 4; k++) mem2r[k] = 0.f;
    float mem3r = 0.f;                  // stage3: warp 0, lanes 0..9

    for (int t = 0; t < T_STEPS; t++) {
        // ================= phase A =====================================
        if (w == 0) {
            // FC + LIF for step t-1 (reads spk2(t-1); stage2(t) starts only
            // after the full barrier below)
            if (t > 0 && lane < 10) fc_stage(s, mem3r, t - 1, b, lane, out);
        } else {
            // x[t][b] -> smem channels-last [row][col*2+ic], row stride 66
            const float* xg = x + ((long long)t * BATCH + b) * 2048;
            for (int idx = tid - 32; idx < 2048; idx += 224) {
                int ic = idx >> 10, pos = idx & 1023;
                int r = pos >> 5, c = pos & 31;
                s[OFF_X + r * 66 + c * 2 + ic] = xg[idx];
            }
            asm volatile("bar.sync 1, 224;" ::: "memory");

            // --- stage 1: conv1(2->12) + pool + LIF (196 tasks) ---
            if (tid < 228) {
                const int task = tid - 32;
                const int ocg = task & 1;
                const int pos = task >> 1;
                const int i1 = pos / 7, jp = pos % 7;
                const int cb = 4 * jp;
                const int ocb = ocg * 6;
                float acc[48];
                #pragma unroll
                for (int k = 0; k < 48; k++) acc[k] = 0.f;

                for (int ry = 0; ry < 6; ry++) {
                    const float2* xr = reinterpret_cast<const float2*>(
                        s + OFF_X + (2 * i1 + ry) * 66 + cb * 2);
                    float2 win[8];
                    #pragma unroll
                    for (int c = 0; c < 8; c++) win[c] = xr[c];
                    bool top = (ry < 5), bot = (ry > 0);
                    int kyt = top ? ry : 4;
                    int kyb = bot ? ry - 1 : 0;
                    #pragma unroll
                    for (int kx = 0; kx < 5; kx++) {
                        #pragma unroll
                        for (int oc = 0; oc < 6; oc++) {
                            float2 wt = *reinterpret_cast<const float2*>(
                                s + OFF_W1 + (((ocb + oc) * 5 + kyt) * 5 + kx) * 2);
                            float2 wb = *reinterpret_cast<const float2*>(
                                s + OFF_W1 + (((ocb + oc) * 5 + kyb) * 5 + kx) * 2);
                            if (!top) { wt.x = 0.f; wt.y = 0.f; }  // exact no-op fmas
                            if (!bot) { wb.x = 0.f; wb.y = 0.f; }
                            #pragma unroll
                            for (int c = 0; c < 4; c++) {
                                float2 xv = win[kx + c];
                                float a0 = acc[oc * 8 + c];
                                float a1 = acc[oc * 8 + 4 + c];
                                a0 = fmaf(wt.x, xv.x, a0);
                                a0 = fmaf(wt.y, xv.y, a0);
                                a1 = fmaf(wb.x, xv.x, a1);
                                a1 = fmaf(wb.y, xv.y, a1);
                                acc[oc * 8 + c]     = a0;
                                acc[oc * 8 + 4 + c] = a1;
                            }
                        }
                    }
                }
                #pragma unroll
                for (int oc = 0; oc < 6; oc++) {
                    float p0 = fmaxf(fmaxf(acc[oc*8+0], acc[oc*8+1]),
                                     fmaxf(acc[oc*8+4], acc[oc*8+5]));
                    float p1 = fmaxf(fmaxf(acc[oc*8+2], acc[oc*8+3]),
                                     fmaxf(acc[oc*8+6], acc[oc*8+7]));
                    float bias = s[OFF_B1 + ocb + oc];
                    // neuron 0: (i1, 2jp), neuron 1: (i1, 2jp+1)
                    float c0 = __fadd_rn(p0, bias);
                    float m0 = mem1r[oc * 2 + 0];
                    float r0 = (m0 > 1.0f) ? 1.0f : 0.0f;
                    m0 = __fsub_rn(__fmaf_rn(0.95f, m0, c0), r0);
                    mem1r[oc * 2 + 0] = m0;
                    s[OFF_S1 + (i1 * 14 + 2 * jp) * 12 + ocb + oc] =
                        (m0 > 1.0f) ? 1.0f : 0.0f;

                    float c1 = __fadd_rn(p1, bias);
                    float m1 = mem1r[oc * 2 + 1];
                    float r1 = (m1 > 1.0f) ? 1.0f : 0.0f;
                    m1 = __fsub_rn(__fmaf_rn(0.95f, m1, c1), r1);
                    mem1r[oc * 2 + 1] = m1;
                    s[OFF_S1 + (i1 * 14 + 2 * jp + 1) * 12 + ocb + oc] =
                        (m1 > 1.0f) ? 1.0f : 0.0f;
                }
            }
        }
        __syncthreads();

        // ================= phase B: stage 2 ============================
        // lane = oc (32), warp w handles pooled positions p = 8m + w (p<25).
        // All spk1 loads warp-uniform broadcasts; weight f4 loads
        // conflict-free (oc stride 300 = 12 mod 32).
        const float* wocb = s + OFF_W2 + lane * 300;
        #pragma unroll
        for (int m = 0; m < 4; m++) {
            int p = 8 * m + w;
            if (p < 25) {
                int i2 = p / 5, j2 = p % 5;
                float a00 = 0.f, a01 = 0.f, a10 = 0.f, a11 = 0.f;
                for (int ky = 0; ky < 5; ky++) {
                    int ra = 2 * i2 + ky;
                    const float4* rowa = reinterpret_cast<const float4*>(
                        s + OFF_S1 + (ra * 14 + 2 * j2) * 12);
                    const float4* rowb = reinterpret_cast<const float4*>(
                        s + OFF_S1 + ((ra + 1) * 14 + 2 * j2) * 12);
                    float4 xc[2][2][3];   // [col parity][row a/b][icf4]
                    #pragma unroll
                    for (int k = 0; k < 3; k++) {
                        xc[0][0][k] = rowa[k];
                        xc[0][1][k] = rowb[k];
                        xc[1][0][k] = rowa[3 + k];
                        xc[1][1][k] = rowb[3 + k];
                    }
                    #pragma unroll
                    for (int kx = 0; kx < 5; kx++) {
                        const float4* wv = reinterpret_cast<const float4*>(
                            wocb + (ky * 5 + kx) * 12);
                        float4 w0 = wv[0], w1 = wv[1], w2 = wv[2];
                        const int L = kx & 1, R = 1 - L;
                        fma12(a00, w0, w1, w2, xc[L][0]);
                        fma12(a01, w0, w1, w2, xc[R][0]);
                        fma12(a10, w0, w1, w2, xc[L][1]);
                        fma12(a11, w0, w1, w2, xc[R][1]);
                        if (kx < 4) {     // slide: col 2j2+kx+2 replaces L
                            #pragma unroll
                            for (int k = 0; k < 3; k++) {
                                xc[L][0][k] = rowa[(kx + 2) * 3 + k];
                                xc[L][1][k] = rowb[(kx + 2) * 3 + k];
                            }
                        }
                    }
                }
                float pm = fmaxf(fmaxf(a00, a01), fmaxf(a10, a11));
                float cur = __fadd_rn(pm, s[OFF_B2 + lane]);
                float mv = mem2r[m];
                float reset = (mv > 1.0f) ? 1.0f : 0.0f;
                mv = __fsub_rn(__fmaf_rn(0.95f, mv, cur), reset);
                mem2r[m] = mv;
                s[OFF_S2 + lane * 25 + p] = (mv > 1.0f) ? 1.0f : 0.0f;
            }
        }
        __syncthreads();
    }

    // final FC for t = T-1
    if (w == 0 && lane < 10)
        fc_stage(s, mem3r, T_STEPS - 1, b, lane, out);
}

extern "C" void kernel_launch(void* const* d_in, const int* in_sizes, int n_in,
                              void* d_out, int out_size) {
    const float* x  = (const float*)d_in[0];
    const float* W1 = (const float*)d_in[1];
    const float* b1 = (const float*)d_in[2];
    const float* W2 = (const float*)d_in[3];
    const float* b2 = (const float*)d_in[4];
    const float* W3 = (const float*)d_in[5];
    const float* b3 = (const float*)d_in[6];
    float* out = (float*)d_out;

    cudaFuncSetAttribute(snn_kernel,
                         cudaFuncAttributeMaxDynamicSharedMemorySize,
                         SMEM_BYTES);
    snn_kernel<<<BATCH, 256, SMEM_BYTES>>>(x, W1, b1, W2, b2, W3, b3, out);
}

// round 5
// speedup vs baseline: 2.5973x; 1.0755x over previous
#include <cuda_runtime.h>

// ---------------------------------------------------------------------------
// Bit-exact fused SNN kernel, v3. One CTA per batch element, T=100 steps.
// PROTECTED arithmetic (bit-exact vs reference, verified rel_err==0.0):
//   conv: per-output sequential FMA in (ky, kx, ic) order
//   FC:   sequential FMA q = 0..799
//   LIF:  m' = fsub(fma(0.95, m, cur), reset)
//   pool-then-bias
// v3 perf changes:
//   - stage2: (ky,kx)-outer / position-inner; weights register-cached per
//     (ky,kx) -> weight LDS 900->75 per thread (crossbar 57K->5K cyc/step)
//   - stage1: peel ry=0 / ry=5 -> no padded zero-FMAs (2880->2400)
// ---------------------------------------------------------------------------

#define T_STEPS 100
#define BATCH   256

constexpr int OFF_W1 = 0;        // w1cl [12][5][5][2]  = 600
constexpr int OFF_B1 = 600;      // 12 (+4 pad)
constexpr int OFF_W2 = 616;      // w2cl [32][25][12]   = 9600 (oc stride 300)
constexpr int OFF_B2 = 10216;    // 32
constexpr int OFF_W3 = 10248;    // [10][804]           = 8040
constexpr int OFF_B3 = 18288;    // 12
constexpr int OFF_X  = 18300;    // x cl [32 rows][66]  = 2112
constexpr int OFF_S1 = 20412;    // spk1 cl [14][14][12] = 2352
constexpr int OFF_S2 = 22764;    // 800 (oc*25 + i*5 + j)
constexpr int SMEM_FLOATS = 23564;
constexpr int SMEM_BYTES  = SMEM_FLOATS * 4;

__device__ __forceinline__ void fma12(float& acc,
                                      const float4& w0, const float4& w1,
                                      const float4& w2, const float4* x) {
    acc = fmaf(w0.x, x[0].x, acc);
    acc = fmaf(w0.y, x[0].y, acc);
    acc = fmaf(w0.z, x[0].z, acc);
    acc = fmaf(w0.w, x[0].w, acc);
    acc = fmaf(w1.x, x[1].x, acc);
    acc = fmaf(w1.y, x[1].y, acc);
    acc = fmaf(w1.z, x[1].z, acc);
    acc = fmaf(w1.w, x[1].w, acc);
    acc = fmaf(w2.x, x[2].x, acc);
    acc = fmaf(w2.y, x[2].y, acc);
    acc = fmaf(w2.z, x[2].z, acc);
    acc = fmaf(w2.w, x[2].w, acc);
}

__device__ __forceinline__ float lif_step(float& mem, float cur) {
    float reset = (mem > 1.0f) ? 1.0f : 0.0f;
    float mn = __fsub_rn(__fmaf_rn(0.95f, mem, cur), reset);
    mem = mn;
    return (mn > 1.0f) ? 1.0f : 0.0f;
}

__device__ __forceinline__ void fc_stage(const float* __restrict__ s,
                                         float& mem3, int t, int b, int k,
                                         float* __restrict__ out) {
    const float4* wr = reinterpret_cast<const float4*>(s + OFF_W3 + k * 804);
    const float4* xv = reinterpret_cast<const float4*>(s + OFF_S2);
    float acc = 0.f;
    #pragma unroll 4
    for (int q = 0; q < 200; q++) {
        float4 w = wr[q], x = xv[q];
        acc = fmaf(x.x, w.x, acc);
        acc = fmaf(x.y, w.y, acc);
        acc = fmaf(x.z, w.z, acc);
        acc = fmaf(x.w, w.w, acc);
    }
    float cur = __fadd_rn(acc, s[OFF_B3 + k]);
    out[((long long)t * BATCH + b) * 10 + k] = lif_step(mem3, cur);
}

__global__ void __launch_bounds__(256, 2) snn_kernel(
    const float* __restrict__ x,
    const float* __restrict__ W1, const float* __restrict__ b1,
    const float* __restrict__ W2, const float* __restrict__ b2,
    const float* __restrict__ W3, const float* __restrict__ b3,
    float* __restrict__ out)
{
    extern __shared__ float s[];
    const int b    = blockIdx.x;
    const int tid  = threadIdx.x;
    const int lane = tid & 31;
    const int w    = tid >> 5;

    for (int i = tid; i < 600; i += 256) {
        int oc = i / 50, r = i % 50, ic = r / 25, k = r % 25;
        s[OFF_W1 + (oc * 25 + k) * 2 + ic] = W1[i];
    }
    for (int i = tid; i < 9600; i += 256) {
        int oc = i / 300, r = i % 300, ic = r / 25, k = r % 25;
        s[OFF_W2 + oc * 300 + k * 12 + ic] = W2[i];
    }
    for (int i = tid; i < 8000; i += 256) {
        int k = i / 800, q = i % 800;
        s[OFF_W3 + k * 804 + q] = W3[i];
    }
    for (int i = tid; i < 12; i += 256) s[OFF_B1 + i] = b1[i];
    for (int i = tid; i < 32; i += 256) s[OFF_B2 + i] = b2[i];
    for (int i = tid; i < 12; i += 256) s[OFF_B3 + i] = (i < 10) ? b3[i] : 0.f;
    __syncthreads();

    float mem1r[12];
    #pragma unroll
    for (int k = 0; k < 12; k++) mem1r[k] = 0.f;
    float mem2r[4];
    #pragma unroll
    for (int k = 0; k < 4; k++) mem2r[k] = 0.f;
    float mem3r = 0.f;

    // stage2 position assignment: lane = oc, warp handles p = 8m + w
    int pim[4], pjm[4];
    #pragma unroll
    for (int m = 0; m < 4; m++) {
        int p = 8 * m + w;
        pim[m] = (p < 25) ? (p / 5) : 0;
        pjm[m] = (p < 25) ? (p % 5) : 0;
    }

    for (int t = 0; t < T_STEPS; t++) {
        // ================= phase A: FC(t-1) || x-load + stage1(t) ==========
        if (w == 0) {
            if (t > 0 && lane < 10) fc_stage(s, mem3r, t - 1, b, lane, out);
        } else {
            const float* xg = x + ((long long)t * BATCH + b) * 2048;
            for (int idx = tid - 32; idx < 2048; idx += 224) {
                int ic = idx >> 10, pos = idx & 1023;
                int r = pos >> 5, c = pos & 31;
                s[OFF_X + r * 66 + c * 2 + ic] = xg[idx];
            }
            asm volatile("bar.sync 1, 224;" ::: "memory");

            // --- stage 1: conv1(2->12) + pool + LIF, boundary-peeled ---
            if (tid < 228) {
                const int task = tid - 32;
                const int ocg = task & 1;
                const int pos = task >> 1;
                const int i1 = pos / 7, jp = pos % 7;
                const int cb = 4 * jp;
                const int ocb = ocg * 6;
                float acc[48];
                #pragma unroll
                for (int k = 0; k < 48; k++) acc[k] = 0.f;

                // macro-ish lambda: apply weight row wky of all 6 oc to window,
                // accumulating into side 0 (a0, offs 0..3) or side 1 (offs 4..7)
                auto apply = [&](int ry, int wky, int side) {
                    const float2* xr = reinterpret_cast<const float2*>(
                        s + OFF_X + (2 * i1 + ry) * 66 + cb * 2);
                    float2 win[8];
                    #pragma unroll
                    for (int c = 0; c < 8; c++) win[c] = xr[c];
                    #pragma unroll
                    for (int kx = 0; kx < 5; kx++) {
                        #pragma unroll
                        for (int oc = 0; oc < 6; oc++) {
                            float2 wv = *reinterpret_cast<const float2*>(
                                s + OFF_W1 + (((ocb + oc) * 5 + wky) * 5 + kx) * 2);
                            #pragma unroll
                            for (int c = 0; c < 4; c++) {
                                float2 xv = win[kx + c];
                                float a = acc[oc * 8 + side * 4 + c];
                                a = fmaf(wv.x, xv.x, a);
                                a = fmaf(wv.y, xv.y, a);
                                acc[oc * 8 + side * 4 + c] = a;
                            }
                        }
                    }
                };
                // both-sides variant: same window, two weight rows
                auto apply2 = [&](int ry) {
                    const float2* xr = reinterpret_cast<const float2*>(
                        s + OFF_X + (2 * i1 + ry) * 66 + cb * 2);
                    float2 win[8];
                    #pragma unroll
                    for (int c = 0; c < 8; c++) win[c] = xr[c];
                    #pragma unroll
                    for (int kx = 0; kx < 5; kx++) {
                        #pragma unroll
                        for (int oc = 0; oc < 6; oc++) {
                            float2 wt = *reinterpret_cast<const float2*>(
                                s + OFF_W1 + (((ocb + oc) * 5 + ry) * 5 + kx) * 2);
                            float2 wb = *reinterpret_cast<const float2*>(
                                s + OFF_W1 + (((ocb + oc) * 5 + (ry - 1)) * 5 + kx) * 2);
                            #pragma unroll
                            for (int c = 0; c < 4; c++) {
                                float2 xv = win[kx + c];
                                float a0 = acc[oc * 8 + c];
                                float a1 = acc[oc * 8 + 4 + c];
                                a0 = fmaf(wt.x, xv.x, a0);
                                a0 = fmaf(wt.y, xv.y, a0);
                                a1 = fmaf(wb.x, xv.x, a1);
                                a1 = fmaf(wb.y, xv.y, a1);
                                acc[oc * 8 + c]     = a0;
                                acc[oc * 8 + 4 + c] = a1;
                            }
                        }
                    }
                };

                apply(0, 0, 0);                 // ry=0: conv row 2i1, ky=0
                apply2(1);
                apply2(2);
                apply2(3);
                apply2(4);
                apply(5, 4, 1);                 // ry=5: conv row 2i1+1, ky=4

                #pragma unroll
                for (int oc = 0; oc < 6; oc++) {
                    float p0 = fmaxf(fmaxf(acc[oc*8+0], acc[oc*8+1]),
                                     fmaxf(acc[oc*8+4], acc[oc*8+5]));
                    float p1 = fmaxf(fmaxf(acc[oc*8+2], acc[oc*8+3]),
                                     fmaxf(acc[oc*8+6], acc[oc*8+7]));
                    float bias = s[OFF_B1 + ocb + oc];
                    s[OFF_S1 + (i1 * 14 + 2 * jp) * 12 + ocb + oc] =
                        lif_step(mem1r[oc * 2 + 0], __fadd_rn(p0, bias));
                    s[OFF_S1 + (i1 * 14 + 2 * jp + 1) * 12 + ocb + oc] =
                        lif_step(mem1r[oc * 2 + 1], __fadd_rn(p1, bias));
                }
            }
        }
        __syncthreads();

        // ================= phase B: stage 2 ================================
        // lane = oc; (ky,kx) outer with weights in regs; positions inner.
        // x loads are warp-uniform broadcasts; weight LDS = 75/thread/step.
        {
            const float* wocb = s + OFF_W2 + lane * 300;
            float a[4][4];
            #pragma unroll
            for (int m = 0; m < 4; m++)
                #pragma unroll
                for (int q = 0; q < 4; q++) a[m][q] = 0.f;

            for (int ky = 0; ky < 5; ky++) {
                #pragma unroll
                for (int kx = 0; kx < 5; kx++) {
                    const float4* wv = reinterpret_cast<const float4*>(
                        wocb + (ky * 5 + kx) * 12);
                    float4 w0 = wv[0], w1 = wv[1], w2 = wv[2];
                    #pragma unroll
                    for (int m = 0; m < 4; m++) {
                        if (8 * m + w < 25) {
                            int colL = 2 * pjm[m] + kx;
                            const float4* ra = reinterpret_cast<const float4*>(
                                s + OFF_S1 + ((2 * pim[m] + ky) * 14 + colL) * 12);
                            const float4* rb = reinterpret_cast<const float4*>(
                                s + OFF_S1 + ((2 * pim[m] + ky + 1) * 14 + colL) * 12);
                            float4 xa0[3] = { ra[0], ra[1], ra[2] };
                            float4 xa1[3] = { ra[3], ra[4], ra[5] };
                            float4 xb0[3] = { rb[0], rb[1], rb[2] };
                            float4 xb1[3] = { rb[3], rb[4], rb[5] };
                            fma12(a[m][0], w0, w1, w2, xa0);
                            fma12(a[m][1], w0, w1, w2, xa1);
                            fma12(a[m][2], w0, w1, w2, xb0);
                            fma12(a[m][3], w0, w1, w2, xb1);
                        }
                    }
                }
            }
            #pragma unroll
            for (int m = 0; m < 4; m++) {
                int p = 8 * m + w;
                if (p < 25) {
                    float pm = fmaxf(fmaxf(a[m][0], a[m][1]),
                                     fmaxf(a[m][2], a[m][3]));
                    float cur = __fadd_rn(pm, s[OFF_B2 + lane]);
                    s[OFF_S2 + lane * 25 + p] = lif_step(mem2r[m], cur);
                }
            }
        }
        __syncthreads();
    }

    if (w == 0 && lane < 10)
        fc_stage(s, mem3r, T_STEPS - 1, b, lane, out);
}

extern "C" void kernel_launch(void* const* d_in, const int* in_sizes, int n_in,
                              void* d_out, int out_size) {
    const float* x  = (const float*)d_in[0];
    const float* W1 = (const float*)d_in[1];
    const float* b1 = (const float*)d_in[2];
    const float* W2 = (const float*)d_in[3];
    const float* b2 = (const float*)d_in[4];
    const float* W3 = (const float*)d_in[5];
    const float* b3 = (const float*)d_in[6];
    float* out = (float*)d_out;

    cudaFuncSetAttribute(snn_kernel,
                         cudaFuncAttributeMaxDynamicSharedMemorySize,
                         SMEM_BYTES);
    snn_kernel<<<BATCH, 256, SMEM_BYTES>>>(x, W1, b1, W2, b2, W3, b3, out);
}

// round 6
// speedup vs baseline: 2.9060x; 1.1189x over previous
#include <cuda_runtime.h>

// ---------------------------------------------------------------------------
// Bit-exact fused SNN kernel, v4: FFMA2 (fma.rn.f32x2) pairing.
// One CTA per batch element, T=100 steps in-kernel.
// PROTECTED arithmetic (rel_err == 0.0 invariant):
//   conv: per-output sequential FMA in (ky, kx, ic) order
//   FC:   sequential FMA q = 0..799
//   LIF:  m' = fsub(fma(0.95, m, cur), reset)
//   pool-then-bias
// FFMA2 performs two INDEPENDENT IEEE fma.rn ops -> each paired chain keeps
// its exact sequential order; pairing never mixes chains.
// v4 changes:
//   - stage2: pair pooled rows (a00,a10)/(a01,a11); spk1 stored in dual
//     row-pair layouts (A: even-based pairs, B: odd-based) ordered
//     [col][rowpair][ic][2rows] so one LDS.128 = two FFMA2 x-operands.
//     Weights packed (w,w) once per (ky,kx) on the idle ALU pipe.
//   - stage1: pair conv rows (a0,a1) sharing x, weight rows (ry,ry-1)
//     pre-paired in smem (w1p); ry=0/5 boundary kept scalar.
// ---------------------------------------------------------------------------

#define T_STEPS 100
#define BATCH   256

typedef unsigned long long u64;

// smem layout (float offsets)
constexpr int OFF_W1  = 0;       // w1 cl [oc][ky][kx][ic2]          = 600
constexpr int OFF_B1  = 600;     // 12 (+4 pad)
constexpr int OFF_W1P = 616;     // paired w1 [oc][ry-1][kx][4]      = 960
constexpr int OFF_W2  = 1576;    // w2 cl [32][25][12]               = 9600
constexpr int OFF_B2  = 11176;   // 32
constexpr int OFF_W3  = 11208;   // [10][804]                        = 8040
constexpr int OFF_B3  = 19248;   // 12
constexpr int OFF_X   = 19260;   // x cl [32 rows][66]               = 2112
constexpr int OFF_S1A = 21372;   // spk1 A [col14][rp7][ic12][2]     = 2352
constexpr int OFF_S1B = 23724;   // spk1 B [col14][rp6][ic12][2]     = 2016
constexpr int OFF_S2  = 25740;   // 800 (oc*25 + i*5 + j)
constexpr int SMEM_FLOATS = 26540;
constexpr int SMEM_BYTES  = SMEM_FLOATS * 4;

__device__ __forceinline__ u64 pack2(float lo, float hi) {
    u64 r;
    asm("mov.b64 %0, {%1, %2};" : "=l"(r) : "f"(lo), "f"(hi));
    return r;
}
__device__ __forceinline__ void unpack2(float& lo, float& hi, u64 v) {
    asm("mov.b64 {%0, %1}, %2;" : "=f"(lo), "=f"(hi) : "l"(v));
}
// d.lo = fma.rn(a.lo, b.lo, d.lo); d.hi = fma.rn(a.hi, b.hi, d.hi)
__device__ __forceinline__ void ffma2(u64& d, u64 a, u64 b) {
    asm("fma.rn.f32x2 %0, %1, %2, %0;" : "+l"(d) : "l"(a), "l"(b));
}

__device__ __forceinline__ float lif_step(float& mem, float cur) {
    float reset = (mem > 1.0f) ? 1.0f : 0.0f;
    float mn = __fsub_rn(__fmaf_rn(0.95f, mem, cur), reset);
    mem = mn;
    return (mn > 1.0f) ? 1.0f : 0.0f;
}

__device__ __forceinline__ void fc_stage(const float* __restrict__ s,
                                         float& mem3, int t, int b, int k,
                                         float* __restrict__ out) {
    const float4* wr = reinterpret_cast<const float4*>(s + OFF_W3 + k * 804);
    const float4* xv = reinterpret_cast<const float4*>(s + OFF_S2);
    float acc = 0.f;
    #pragma unroll 4
    for (int q = 0; q < 200; q++) {
        float4 w = wr[q], x = xv[q];
        acc = fmaf(x.x, w.x, acc);
        acc = fmaf(x.y, w.y, acc);
        acc = fmaf(x.z, w.z, acc);
        acc = fmaf(x.w, w.w, acc);
    }
    float cur = __fadd_rn(acc, s[OFF_B3 + k]);
    out[((long long)t * BATCH + b) * 10 + k] = lif_step(mem3, cur);
}

__global__ void __launch_bounds__(256, 2) snn_kernel(
    const float* __restrict__ x,
    const float* __restrict__ W1, const float* __restrict__ b1,
    const float* __restrict__ W2, const float* __restrict__ b2,
    const float* __restrict__ W3, const float* __restrict__ b3,
    float* __restrict__ out)
{
    extern __shared__ float s[];
    const int b    = blockIdx.x;
    const int tid  = threadIdx.x;
    const int lane = tid & 31;
    const int w    = tid >> 5;

    // --- weights -> smem ---
    for (int i = tid; i < 600; i += 256) {
        int oc = i / 50, r = i % 50, ic = r / 25, k = r % 25;
        s[OFF_W1 + (oc * 25 + k) * 2 + ic] = W1[i];
    }
    // paired conv1 weights: [oc][ry-1 in 0..3][kx][{(ry,ic0),(ry-1,ic0),(ry,ic1),(ry-1,ic1)}]
    for (int i = tid; i < 960; i += 256) {
        int q = i & 3, idx = i >> 2;
        int kx = idx % 5, ryp = (idx / 5) % 4, oc = idx / 20;
        int ry = ryp + 1;
        int ic = q >> 1;
        int useKy = (q & 1) ? (ry - 1) : ry;
        s[OFF_W1P + i] = W1[oc * 50 + ic * 25 + useKy * 5 + kx];
    }
    for (int i = tid; i < 9600; i += 256) {
        int oc = i / 300, r = i % 300, ic = r / 25, k = r % 25;
        s[OFF_W2 + oc * 300 + k * 12 + ic] = W2[i];
    }
    for (int i = tid; i < 8000; i += 256) {
        int k = i / 800, q = i % 800;
        s[OFF_W3 + k * 804 + q] = W3[i];
    }
    for (int i = tid; i < 12; i += 256) s[OFF_B1 + i] = b1[i];
    for (int i = tid; i < 32; i += 256) s[OFF_B2 + i] = b2[i];
    for (int i = tid; i < 12; i += 256) s[OFF_B3 + i] = (i < 10) ? b3[i] : 0.f;
    __syncthreads();

    float mem1r[12];
    #pragma unroll
    for (int k = 0; k < 12; k++) mem1r[k] = 0.f;
    float mem2r[4];
    #pragma unroll
    for (int k = 0; k < 4; k++) mem2r[k] = 0.f;
    float mem3r = 0.f;

    // stage2 assignment: lane = oc, warp handles positions p = 8m + w
    int pim[4], pjm[4];
    #pragma unroll
    for (int m = 0; m < 4; m++) {
        int p = 8 * m + w;
        pim[m] = (p < 25) ? (p / 5) : 0;
        pjm[m] = (p < 25) ? (p % 5) : 0;
    }

    for (int t = 0; t < T_STEPS; t++) {
        // ============ phase A: FC(t-1) on warp0 || x-load + stage1 =========
        if (w == 0) {
            if (t > 0 && lane < 10) fc_stage(s, mem3r, t - 1, b, lane, out);
        } else {
            const float* xg = x + ((long long)t * BATCH + b) * 2048;
            for (int idx = tid - 32; idx < 2048; idx += 224) {
                int ic = idx >> 10, pos = idx & 1023;
                int r = pos >> 5, c = pos & 31;
                s[OFF_X + r * 66 + c * 2 + ic] = xg[idx];
            }
            asm volatile("bar.sync 1, 224;" ::: "memory");

            if (tid < 228) {
                const int task = tid - 32;
                const int ocg = task & 1;
                const int pos = task >> 1;
                const int i1 = pos / 7, jp = pos % 7;
                const int cb = 4 * jp;
                const int ocb = ocg * 6;

                // --- ry = 0: scalar, side0 (conv row 2i1, ky=0) ---
                float a0s[24];
                #pragma unroll
                for (int k = 0; k < 24; k++) a0s[k] = 0.f;
                {
                    const float2* xr = reinterpret_cast<const float2*>(
                        s + OFF_X + (2 * i1) * 66 + cb * 2);
                    float2 win[8];
                    #pragma unroll
                    for (int c = 0; c < 8; c++) win[c] = xr[c];
                    #pragma unroll
                    for (int kx = 0; kx < 5; kx++)
                        #pragma unroll
                        for (int oc = 0; oc < 6; oc++) {
                            float2 wv = *reinterpret_cast<const float2*>(
                                s + OFF_W1 + ((ocb + oc) * 25 + kx) * 2);
                            #pragma unroll
                            for (int c = 0; c < 4; c++) {
                                float a = a0s[oc * 4 + c];
                                a = fmaf(wv.x, win[kx + c].x, a);
                                a = fmaf(wv.y, win[kx + c].y, a);
                                a0s[oc * 4 + c] = a;
                            }
                        }
                }
                // pack (a0, 0) pairs
                u64 P[24];
                #pragma unroll
                for (int k = 0; k < 24; k++) P[k] = pack2(a0s[k], 0.f);

                // --- ry = 1..4: paired (side0 ky=ry, side1 ky=ry-1) ---
                #pragma unroll
                for (int ry = 1; ry <= 4; ry++) {
                    const float2* xr = reinterpret_cast<const float2*>(
                        s + OFF_X + (2 * i1 + ry) * 66 + cb * 2);
                    float2 win[8];
                    #pragma unroll
                    for (int c = 0; c < 8; c++) win[c] = xr[c];
                    u64 xd[16];
                    #pragma unroll
                    for (int j = 0; j < 8; j++) {
                        xd[2 * j]     = pack2(win[j].x, win[j].x);
                        xd[2 * j + 1] = pack2(win[j].y, win[j].y);
                    }
                    #pragma unroll
                    for (int kx = 0; kx < 5; kx++)
                        #pragma unroll
                        for (int oc = 0; oc < 6; oc++) {
                            ulonglong2 wq = *reinterpret_cast<const ulonglong2*>(
                                s + OFF_W1P +
                                (((ocb + oc) * 4 + (ry - 1)) * 5 + kx) * 4);
                            #pragma unroll
                            for (int c = 0; c < 4; c++) {
                                ffma2(P[oc * 4 + c], wq.x, xd[2 * (kx + c)]);
                                ffma2(P[oc * 4 + c], wq.y, xd[2 * (kx + c) + 1]);
                            }
                        }
                }
                // unpack
                float a1s[24];
                #pragma unroll
                for (int k = 0; k < 24; k++) unpack2(a0s[k], a1s[k], P[k]);

                // --- ry = 5: scalar, side1 (conv row 2i1+1, ky=4) ---
                {
                    const float2* xr = reinterpret_cast<const float2*>(
                        s + OFF_X + (2 * i1 + 5) * 66 + cb * 2);
                    float2 win[8];
                    #pragma unroll
                    for (int c = 0; c < 8; c++) win[c] = xr[c];
                    #pragma unroll
                    for (int kx = 0; kx < 5; kx++)
                        #pragma unroll
                        for (int oc = 0; oc < 6; oc++) {
                            float2 wv = *reinterpret_cast<const float2*>(
                                s + OFF_W1 + ((ocb + oc) * 25 + 20 + kx) * 2);
                            #pragma unroll
                            for (int c = 0; c < 4; c++) {
                                float a = a1s[oc * 4 + c];
                                a = fmaf(wv.x, win[kx + c].x, a);
                                a = fmaf(wv.y, win[kx + c].y, a);
                                a1s[oc * 4 + c] = a;
                            }
                        }
                }

                // pool + LIF + dual-layout spike stores
                #pragma unroll
                for (int oc = 0; oc < 6; oc++) {
                    float p0 = fmaxf(fmaxf(a0s[oc*4+0], a0s[oc*4+1]),
                                     fmaxf(a1s[oc*4+0], a1s[oc*4+1]));
                    float p1 = fmaxf(fmaxf(a0s[oc*4+2], a0s[oc*4+3]),
                                     fmaxf(a1s[oc*4+2], a1s[oc*4+3]));
                    float bias = s[OFF_B1 + ocb + oc];
                    float sp0 = lif_step(mem1r[oc * 2 + 0], __fadd_rn(p0, bias));
                    float sp1 = lif_step(mem1r[oc * 2 + 1], __fadd_rn(p1, bias));
                    const int r = i1, ch = ocb + oc;
                    const int rpA = r >> 1, qA = r & 1;
                    const int c0 = 2 * jp, c1 = 2 * jp + 1;
                    s[OFF_S1A + ((c0 * 7 + rpA) * 12 + ch) * 2 + qA] = sp0;
                    s[OFF_S1A + ((c1 * 7 + rpA) * 12 + ch) * 2 + qA] = sp1;
                    if (r >= 1 && r <= 12) {
                        const int rpB = (r - 1) >> 1, qB = 1 - (r & 1);
                        s[OFF_S1B + ((c0 * 6 + rpB) * 12 + ch) * 2 + qB] = sp0;
                        s[OFF_S1B + ((c1 * 6 + rpB) * 12 + ch) * 2 + qB] = sp1;
                    }
                }
            }
        }
        __syncthreads();

        // ============ phase B: stage 2, row-paired FFMA2 ===================
        {
            const float* wocb = s + OFF_W2 + lane * 300;
            u64 A0[4], A1[4];
            #pragma unroll
            for (int m = 0; m < 4; m++) { A0[m] = 0ULL; A1[m] = 0ULL; }

            for (int ky = 0; ky < 5; ky++) {
                // per-(ky,m): base pointer at col 2*pjm (layout by ra parity)
                const float* pbase[4];
                int cs[4];
                #pragma unroll
                for (int m = 0; m < 4; m++) {
                    int ra = 2 * pim[m] + ky;
                    if (ra & 1) {
                        cs[m] = 144;   // B col stride (6 rp * 24)
                        pbase[m] = s + OFF_S1B + ((ra - 1) >> 1) * 24
                                   + 2 * pjm[m] * 144;
                    } else {
                        cs[m] = 168;   // A col stride (7 rp * 24)
                        pbase[m] = s + OFF_S1A + (ra >> 1) * 24
                                   + 2 * pjm[m] * 168;
                    }
                }
                #pragma unroll
                for (int kx = 0; kx < 5; kx++) {
                    const float4* wv4 = reinterpret_cast<const float4*>(
                        wocb + (ky * 5 + kx) * 12);
                    float4 w0 = wv4[0], w1 = wv4[1], w2 = wv4[2];
                    u64 wp[12];
                    wp[0]  = pack2(w0.x, w0.x); wp[1]  = pack2(w0.y, w0.y);
                    wp[2]  = pack2(w0.z, w0.z); wp[3]  = pack2(w0.w, w0.w);
                    wp[4]  = pack2(w1.x, w1.x); wp[5]  = pack2(w1.y, w1.y);
                    wp[6]  = pack2(w1.z, w1.z); wp[7]  = pack2(w1.w, w1.w);
                    wp[8]  = pack2(w2.x, w2.x); wp[9]  = pack2(w2.y, w2.y);
                    wp[10] = pack2(w2.z, w2.z); wp[11] = pack2(w2.w, w2.w);
                    #pragma unroll
                    for (int m = 0; m < 4; m++) {
                        if (8 * m + w < 25) {
                            const ulonglong2* xL =
                                reinterpret_cast<const ulonglong2*>(
                                    pbase[m] + kx * cs[m]);
                            const ulonglong2* xR =
                                reinterpret_cast<const ulonglong2*>(
                                    pbase[m] + (kx + 1) * cs[m]);
                            #pragma unroll
                            for (int j = 0; j < 6; j++) {
                                ulonglong2 xx = xL[j];
                                ffma2(A0[m], wp[2 * j],     xx.x);
                                ffma2(A0[m], wp[2 * j + 1], xx.y);
                            }
                            #pragma unroll
                            for (int j = 0; j < 6; j++) {
                                ulonglong2 xx = xR[j];
                                ffma2(A1[m], wp[2 * j],     xx.x);
                                ffma2(A1[m], wp[2 * j + 1], xx.y);
                            }
                        }
                    }
                }
            }
            #pragma unroll
            for (int m = 0; m < 4; m++) {
                int p = 8 * m + w;
                if (p < 25) {
                    float a00, a10, a01, a11;
                    unpack2(a00, a10, A0[m]);
                    unpack2(a01, a11, A1[m]);
                    float pm = fmaxf(fmaxf(a00, a01), fmaxf(a10, a11));
                    float cur = __fadd_rn(pm, s[OFF_B2 + lane]);
                    s[OFF_S2 + lane * 25 + p] = lif_step(mem2r[m], cur);
                }
            }
        }
        __syncthreads();
    }

    if (w == 0 && lane < 10)
        fc_stage(s, mem3r, T_STEPS - 1, b, lane, out);
}

extern "C" void kernel_launch(void* const* d_in, const int* in_sizes, int n_in,
                              void* d_out, int out_size) {
    const float* x  = (const float*)d_in[0];
    const float* W1 = (const float*)d_in[1];
    const float* b1 = (const float*)d_in[2];
    const float* W2 = (const float*)d_in[3];
    const float* b2 = (const float*)d_in[4];
    const float* W3 = (const float*)d_in[5];
    const float* b3 = (const float*)d_in[6];
    float* out = (float*)d_out;

    cudaFuncSetAttribute(snn_kernel,
                         cudaFuncAttributeMaxDynamicSharedMemorySize,
                         SMEM_BYTES);
    snn_kernel<<<BATCH, 256, SMEM_BYTES>>>(x, W1, b1, W2, b2, W3, b3, out);
}

// round 7
// speedup vs baseline: 3.3358x; 1.1479x over previous
#include <cuda_runtime.h>

// ---------------------------------------------------------------------------
// Bit-exact fused SNN kernel, v5: stage2 column-rolling (single-load window
// columns, dual rolling weight banks) + stage2 position rebalance.
// One CTA per batch element, T=100 steps in-kernel.
// PROTECTED arithmetic (rel_err == 0.0 invariant):
//   conv: per-output sequential FMA in (ky, kx, ic) order
//   FC:   sequential FMA q = 0..799
//   LIF:  m' = fsub(fma(0.95, m, cur), reset)
//   pool-then-bias
// FFMA2 = two INDEPENDENT IEEE fma.rn; pairing never mixes chains.
// ---------------------------------------------------------------------------

#define T_STEPS 100
#define BATCH   256

typedef unsigned long long u64;

// smem layout (float offsets)
constexpr int OFF_W1  = 0;       // w1 cl [oc][ky][kx][ic2]          = 600
constexpr int OFF_B1  = 600;     // 12 (+4 pad)
constexpr int OFF_W1P = 616;     // paired w1 [oc][ry-1][kx][4]      = 960
constexpr int OFF_W2  = 1576;    // w2 cl [32][25][12]               = 9600
constexpr int OFF_B2  = 11176;   // 32
constexpr int OFF_W3  = 11208;   // [10][804]                        = 8040
constexpr int OFF_B3  = 19248;   // 12
constexpr int OFF_X   = 19260;   // x cl [32 rows][66]               = 2112
constexpr int OFF_S1A = 21372;   // spk1 A [col14][rp7][ic12][2]     = 2352
constexpr int OFF_S1B = 23724;   // spk1 B [col14][rp6][ic12][2]     = 2016
constexpr int OFF_S2  = 25740;   // 800 (oc*25 + i*5 + j)
constexpr int SMEM_FLOATS = 26540;
constexpr int SMEM_BYTES  = SMEM_FLOATS * 4;

__device__ __forceinline__ u64 pack2(float lo, float hi) {
    u64 r;
    asm("mov.b64 %0, {%1, %2};" : "=l"(r) : "f"(lo), "f"(hi));
    return r;
}
__device__ __forceinline__ void unpack2(float& lo, float& hi, u64 v) {
    asm("mov.b64 {%0, %1}, %2;" : "=f"(lo), "=f"(hi) : "l"(v));
}
// d.lo = fma.rn(a.lo, b.lo, d.lo); d.hi = fma.rn(a.hi, b.hi, d.hi)
__device__ __forceinline__ void ffma2(u64& d, u64 a, u64 b) {
    asm("fma.rn.f32x2 %0, %1, %2, %0;" : "+l"(d) : "l"(a), "l"(b));
}

__device__ __forceinline__ float lif_step(float& mem, float cur) {
    float reset = (mem > 1.0f) ? 1.0f : 0.0f;
    float mn = __fsub_rn(__fmaf_rn(0.95f, mem, cur), reset);
    mem = mn;
    return (mn > 1.0f) ? 1.0f : 0.0f;
}

__device__ __forceinline__ void fc_stage(const float* __restrict__ s,
                                         float& mem3, int t, int b, int k,
                                         float* __restrict__ out) {
    const float4* wr = reinterpret_cast<const float4*>(s + OFF_W3 + k * 804);
    const float4* xv = reinterpret_cast<const float4*>(s + OFF_S2);
    float acc = 0.f;
    #pragma unroll 4
    for (int q = 0; q < 200; q++) {
        float4 w = wr[q], x = xv[q];
        acc = fmaf(x.x, w.x, acc);
        acc = fmaf(x.y, w.y, acc);
        acc = fmaf(x.z, w.z, acc);
        acc = fmaf(x.w, w.w, acc);
    }
    float cur = __fadd_rn(acc, s[OFF_B3 + k]);
    out[((long long)t * BATCH + b) * 10 + k] = lif_step(mem3, cur);
}

__global__ void __launch_bounds__(256, 2) snn_kernel(
    const float* __restrict__ x,
    const float* __restrict__ W1, const float* __restrict__ b1,
    const float* __restrict__ W2, const float* __restrict__ b2,
    const float* __restrict__ W3, const float* __restrict__ b3,
    float* __restrict__ out)
{
    extern __shared__ float s[];
    const int b    = blockIdx.x;
    const int tid  = threadIdx.x;
    const int lane = tid & 31;
    const int w    = tid >> 5;

    // --- weights -> smem ---
    for (int i = tid; i < 600; i += 256) {
        int oc = i / 50, r = i % 50, ic = r / 25, k = r % 25;
        s[OFF_W1 + (oc * 25 + k) * 2 + ic] = W1[i];
    }
    // paired conv1 weights: [oc][ry-1][kx][{(ry,ic0),(ry-1,ic0),(ry,ic1),(ry-1,ic1)}]
    for (int i = tid; i < 960; i += 256) {
        int q = i & 3, idx = i >> 2;
        int kx = idx % 5, ryp = (idx / 5) % 4, oc = idx / 20;
        int ry = ryp + 1;
        int ic = q >> 1;
        int useKy = (q & 1) ? (ry - 1) : ry;
        s[OFF_W1P + i] = W1[oc * 50 + ic * 25 + useKy * 5 + kx];
    }
    for (int i = tid; i < 9600; i += 256) {
        int oc = i / 300, r = i % 300, ic = r / 25, k = r % 25;
        s[OFF_W2 + oc * 300 + k * 12 + ic] = W2[i];
    }
    for (int i = tid; i < 8000; i += 256) {
        int k = i / 800, q = i % 800;
        s[OFF_W3 + k * 804 + q] = W3[i];
    }
    for (int i = tid; i < 12; i += 256) s[OFF_B1 + i] = b1[i];
    for (int i = tid; i < 32; i += 256) s[OFF_B2 + i] = b2[i];
    for (int i = tid; i < 12; i += 256) s[OFF_B3 + i] = (i < 10) ? b3[i] : 0.f;
    __syncthreads();

    float mem1r[12];
    #pragma unroll
    for (int k = 0; k < 12; k++) mem1r[k] = 0.f;
    float mem2r[4];
    #pragma unroll
    for (int k = 0; k < 4; k++) mem2r[k] = 0.f;
    float mem3r = 0.f;

    // stage2 positions: m<3 -> p = 8m + w (3 per warp); m=3 -> p=24, warp 7 only
    const bool has4 = (w == 7);
    int pim[4], pjm[4];
    #pragma unroll
    for (int m = 0; m < 4; m++) {
        int p = (m < 3) ? (8 * m + w) : 24;
        pim[m] = p / 5;
        pjm[m] = p % 5;
    }

    for (int t = 0; t < T_STEPS; t++) {
        // ============ phase A: FC(t-1) on warp0 || x-load + stage1 =========
        if (w == 0) {
            if (t > 0 && lane < 10) fc_stage(s, mem3r, t - 1, b, lane, out);
        } else {
            const float* xg = x + ((long long)t * BATCH + b) * 2048;
            for (int idx = tid - 32; idx < 2048; idx += 224) {
                int ic = idx >> 10, pos = idx & 1023;
                int r = pos >> 5, c = pos & 31;
                s[OFF_X + r * 66 + c * 2 + ic] = xg[idx];
            }
            asm volatile("bar.sync 1, 224;" ::: "memory");

            if (tid < 228) {
                const int task = tid - 32;
                const int ocg = task & 1;
                const int pos = task >> 1;
                const int i1 = pos / 7, jp = pos % 7;
                const int cb = 4 * jp;
                const int ocb = ocg * 6;

                // --- ry = 0: scalar, side0 (conv row 2i1, ky=0) ---
                float a0s[24];
                #pragma unroll
                for (int k = 0; k < 24; k++) a0s[k] = 0.f;
                {
                    const float2* xr = reinterpret_cast<const float2*>(
                        s + OFF_X + (2 * i1) * 66 + cb * 2);
                    float2 win[8];
                    #pragma unroll
                    for (int c = 0; c < 8; c++) win[c] = xr[c];
                    #pragma unroll
                    for (int kx = 0; kx < 5; kx++)
                        #pragma unroll
                        for (int oc = 0; oc < 6; oc++) {
                            float2 wv = *reinterpret_cast<const float2*>(
                                s + OFF_W1 + ((ocb + oc) * 25 + kx) * 2);
                            #pragma unroll
                            for (int c = 0; c < 4; c++) {
                                float a = a0s[oc * 4 + c];
                                a = fmaf(wv.x, win[kx + c].x, a);
                                a = fmaf(wv.y, win[kx + c].y, a);
                                a0s[oc * 4 + c] = a;
                            }
                        }
                }
                u64 P[24];
                #pragma unroll
                for (int k = 0; k < 24; k++) P[k] = pack2(a0s[k], 0.f);

                // --- ry = 1..4: paired (side0 ky=ry, side1 ky=ry-1) ---
                #pragma unroll
                for (int ry = 1; ry <= 4; ry++) {
                    const float2* xr = reinterpret_cast<const float2*>(
                        s + OFF_X + (2 * i1 + ry) * 66 + cb * 2);
                    float2 win[8];
                    #pragma unroll
                    for (int c = 0; c < 8; c++) win[c] = xr[c];
                    u64 xd[16];
                    #pragma unroll
                    for (int j = 0; j < 8; j++) {
                        xd[2 * j]     = pack2(win[j].x, win[j].x);
                        xd[2 * j + 1] = pack2(win[j].y, win[j].y);
                    }
                    #pragma unroll
                    for (int kx = 0; kx < 5; kx++)
                        #pragma unroll
                        for (int oc = 0; oc < 6; oc++) {
                            ulonglong2 wq = *reinterpret_cast<const ulonglong2*>(
                                s + OFF_W1P +
                                (((ocb + oc) * 4 + (ry - 1)) * 5 + kx) * 4);
                            #pragma unroll
                            for (int c = 0; c < 4; c++) {
                                ffma2(P[oc * 4 + c], wq.x, xd[2 * (kx + c)]);
                                ffma2(P[oc * 4 + c], wq.y, xd[2 * (kx + c) + 1]);
                            }
                        }
                }
                float a1s[24];
                #pragma unroll
                for (int k = 0; k < 24; k++) unpack2(a0s[k], a1s[k], P[k]);

                // --- ry = 5: scalar, side1 (conv row 2i1+1, ky=4) ---
                {
                    const float2* xr = reinterpret_cast<const float2*>(
                        s + OFF_X + (2 * i1 + 5) * 66 + cb * 2);
                    float2 win[8];
                    #pragma unroll
                    for (int c = 0; c < 8; c++) win[c] = xr[c];
                    #pragma unroll
                    for (int kx = 0; kx < 5; kx++)
                        #pragma unroll
                        for (int oc = 0; oc < 6; oc++) {
                            float2 wv = *reinterpret_cast<const float2*>(
                                s + OFF_W1 + ((ocb + oc) * 25 + 20 + kx) * 2);
                            #pragma unroll
                            for (int c = 0; c < 4; c++) {
                                float a = a1s[oc * 4 + c];
                                a = fmaf(wv.x, win[kx + c].x, a);
                                a = fmaf(wv.y, win[kx + c].y, a);
                                a1s[oc * 4 + c] = a;
                            }
                        }
                }

                // pool + LIF + dual-layout spike stores
                #pragma unroll
                for (int oc = 0; oc < 6; oc++) {
                    float p0 = fmaxf(fmaxf(a0s[oc*4+0], a0s[oc*4+1]),
                                     fmaxf(a1s[oc*4+0], a1s[oc*4+1]));
                    float p1 = fmaxf(fmaxf(a0s[oc*4+2], a0s[oc*4+3]),
                                     fmaxf(a1s[oc*4+2], a1s[oc*4+3]));
                    float bias = s[OFF_B1 + ocb + oc];
                    float sp0 = lif_step(mem1r[oc * 2 + 0], __fadd_rn(p0, bias));
                    float sp1 = lif_step(mem1r[oc * 2 + 1], __fadd_rn(p1, bias));
                    const int r = i1, ch = ocb + oc;
                    const int rpA = r >> 1, qA = r & 1;
                    const int c0 = 2 * jp, c1 = 2 * jp + 1;
                    s[OFF_S1A + ((c0 * 7 + rpA) * 12 + ch) * 2 + qA] = sp0;
                    s[OFF_S1A + ((c1 * 7 + rpA) * 12 + ch) * 2 + qA] = sp1;
                    if (r >= 1 && r <= 12) {
                        const int rpB = (r - 1) >> 1, qB = 1 - (r & 1);
                        s[OFF_S1B + ((c0 * 6 + rpB) * 12 + ch) * 2 + qB] = sp0;
                        s[OFF_S1B + ((c1 * 6 + rpB) * 12 + ch) * 2 + qB] = sp1;
                    }
                }
            }
        }
        __syncthreads();

        // ============ phase B: stage 2, column-rolling FFMA2 ===============
        // lane = oc. For each (ky, window-col c): load col ONCE (6 LDS.128
        // broadcast), apply to A0 (kx=c, weights wcur) and A1 (kx=c-1,
        // weights wprev). Chain orders preserved exactly.
        {
            const float* wocb = s + OFF_W2 + lane * 300;
            u64 A0[4], A1[4];
            #pragma unroll
            for (int m = 0; m < 4; m++) { A0[m] = 0ULL; A1[m] = 0ULL; }

            for (int ky = 0; ky < 5; ky++) {
                const float* pb[4];
                int cs4[4];
                #pragma unroll
                for (int m = 0; m < 4; m++) {
                    int ra = 2 * pim[m] + ky;
                    if (ra & 1) {
                        cs4[m] = 144;
                        pb[m] = s + OFF_S1B + ((ra - 1) >> 1) * 24
                                + 2 * pjm[m] * 144;
                    } else {
                        cs4[m] = 168;
                        pb[m] = s + OFF_S1A + (ra >> 1) * 24
                                + 2 * pjm[m] * 168;
                    }
                }
                u64 wcur[12], wprev[12];
                #pragma unroll
                for (int j = 0; j < 12; j++) { wcur[j] = 0ULL; wprev[j] = 0ULL; }
                #pragma unroll
                for (int c = 0; c < 6; c++) {
                    #pragma unroll
                    for (int j = 0; j < 12; j++) wprev[j] = wcur[j];
                    if (c < 5) {
                        const float4* wv4 = reinterpret_cast<const float4*>(
                            wocb + (ky * 5 + c) * 12);
                        float4 w0 = wv4[0], w1 = wv4[1], w2 = wv4[2];
                        wcur[0]  = pack2(w0.x, w0.x); wcur[1]  = pack2(w0.y, w0.y);
                        wcur[2]  = pack2(w0.z, w0.z); wcur[3]  = pack2(w0.w, w0.w);
                        wcur[4]  = pack2(w1.x, w1.x); wcur[5]  = pack2(w1.y, w1.y);
                        wcur[6]  = pack2(w1.z, w1.z); wcur[7]  = pack2(w1.w, w1.w);
                        wcur[8]  = pack2(w2.x, w2.x); wcur[9]  = pack2(w2.y, w2.y);
                        wcur[10] = pack2(w2.z, w2.z); wcur[11] = pack2(w2.w, w2.w);
                    }
                    #pragma unroll
                    for (int m = 0; m < 4; m++) {
                        if (m < 3 || has4) {
                            const ulonglong2* xc =
                                reinterpret_cast<const ulonglong2*>(
                                    pb[m] + c * cs4[m]);
                            ulonglong2 x0 = xc[0], x1 = xc[1], x2 = xc[2];
                            ulonglong2 x3 = xc[3], x4 = xc[4], x5 = xc[5];
                            if (c < 5) {
                                ffma2(A0[m], wcur[0],  x0.x);
                                ffma2(A0[m], wcur[1],  x0.y);
                                ffma2(A0[m], wcur[2],  x1.x);
                                ffma2(A0[m], wcur[3],  x1.y);
                                ffma2(A0[m], wcur[4],  x2.x);
                                ffma2(A0[m], wcur[5],  x2.y);
                                ffma2(A0[m], wcur[6],  x3.x);
                                ffma2(A0[m], wcur[7],  x3.y);
                                ffma2(A0[m], wcur[8],  x4.x);
                                ffma2(A0[m], wcur[9],  x4.y);
                                ffma2(A0[m], wcur[10], x5.x);
                                ffma2(A0[m], wcur[11], x5.y);
                            }
                            if (c >= 1) {
                                ffma2(A1[m], wprev[0],  x0.x);
                                ffma2(A1[m], wprev[1],  x0.y);
                                ffma2(A1[m], wprev[2],  x1.x);
                                ffma2(A1[m], wprev[3],  x1.y);
                                ffma2(A1[m], wprev[4],  x2.x);
                                ffma2(A1[m], wprev[5],  x2.y);
                                ffma2(A1[m], wprev[6],  x3.x);
                                ffma2(A1[m], wprev[7],  x3.y);
                                ffma2(A1[m], wprev[8],  x4.x);
                                ffma2(A1[m], wprev[9],  x4.y);
                                ffma2(A1[m], wprev[10], x5.x);
                                ffma2(A1[m], wprev[11], x5.y);
                            }
                        }
                    }
                }
            }
            #pragma unroll
            for (int m = 0; m < 4; m++) {
                if (m < 3 || has4) {
                    int p = (m < 3) ? (8 * m + w) : 24;
                    float a00, a10, a01, a11;
                    unpack2(a00, a10, A0[m]);
                    unpack2(a01, a11, A1[m]);
                    float pm = fmaxf(fmaxf(a00, a01), fmaxf(a10, a11));
                    float cur = __fadd_rn(pm, s[OFF_B2 + lane]);
                    s[OFF_S2 + lane * 25 + p] = lif_step(mem2r[m], cur);
                }
            }
        }
        __syncthreads();
    }

    if (w == 0 && lane < 10)
        fc_stage(s, mem3r, T_STEPS - 1, b, lane, out);
}

extern "C" void kernel_launch(void* const* d_in, const int* in_sizes, int n_in,
                              void* d_out, int out_size) {
    const float* x  = (const float*)d_in[0];
    const float* W1 = (const float*)d_in[1];
    const float* b1 = (const float*)d_in[2];
    const float* W2 = (const float*)d_in[3];
    const float* b2 = (const float*)d_in[4];
    const float* W3 = (const float*)d_in[5];
    const float* b3 = (const float*)d_in[6];
    float* out = (float*)d_out;

    cudaFuncSetAttribute(snn_kernel,
                         cudaFuncAttributeMaxDynamicSharedMemorySize,
                         SMEM_BYTES);
    snn_kernel<<<BATCH, 256, SMEM_BYTES>>>(x, W1, b1, W2, b2, W3, b3, out);
}